// round 7
// baseline (speedup 1.0000x reference)
#include <cuda_runtime.h>
#include <math.h>

// iDDPMPrecond: (c_skip=1, c_out=-s, c_in=1/sqrt(s^2+1), c_noise=M-1-argmin_j|s-u_j|)
//
// Closed form: recurrence telescopes to 1+u[j]^2 = A/alpha_bar(j), A=alpha_bar(M),
// alpha_bar(j)=sin^2(c*j), c=pi/(2*M*(1+C2)). Invert analytically:
//   j_real = asin(sqrtA * rsqrt(1+s^2)) / c   (reuses c_in); error ~0.005 idx.
// For a strictly decreasing table, |s-u[j]| is unimodal, so the exact argmin is
// one of the TWO indices bracketing the continuous crossing: {floor(jf), floor(jf)+1}.
// 2 probe loads, tie -> smaller index (matches jnp.argmin).

__global__ __launch_bounds__(256)
void precond_kernel(const float* __restrict__ sigma,
                    const float* __restrict__ u,
                    float* __restrict__ out_base,      // c_skip region
                    float* __restrict__ o_out,         // c_out
                    float* __restrict__ o_in,          // c_in
                    float* __restrict__ o_noise,       // c_noise
                    int B, int M, int skip_count,
                    float sqrtA, float inv_c)
{
    int tid = blockIdx.x * blockDim.x + threadIdx.x;

    if (tid < skip_count) out_base[tid] = 1.0f;
    if (tid >= B) return;

    float s  = sigma[tid];
    float ci = rsqrtf(fmaf(s, s, 1.0f));     // c_in

    // Analytic crossing index; issue probe loads ASAP.
    float jf = asinf(sqrtA * ci) * inv_c;
    int j_lo = (int)floorf(jf);
    j_lo = max(0, min(M - 1, j_lo));

    float u_lo = __ldg(&u[j_lo]);
    float u_hi = __ldg(&u[j_lo + 1]);

    o_out[tid] = -s;
    o_in[tid]  = ci;

    float d_lo = fabsf(s - u_lo);
    float d_hi = fabsf(s - u_hi);
    int best_j = (d_hi < d_lo) ? (j_lo + 1) : j_lo;   // strict <: tie -> first index

    o_noise[tid] = (float)(M - 1 - best_j);
}

extern "C" void kernel_launch(void* const* d_in, const int* in_sizes, int n_in,
                              void* d_out, int out_size)
{
    // inputs per metadata order: x (unused), sigma, u, M
    const float* sigma = (const float*)d_in[1];
    const float* u     = (const float*)d_in[2];
    const int B  = in_sizes[1];
    const int nU = in_sizes[2];
    const int M  = nU - 1;

    // Flattened tuple layout: [c_skip (skip elems)] [c_out B] [c_in B] [c_noise B]
    int skip = out_size - 3 * B;
    if (skip < 0) skip = 0;

    float* ob = (float*)d_out;

    const double PI = 3.14159265358979323846;
    const double C2 = 0.008;
    const double c  = PI * 0.5 / ((double)M * (1.0 + C2));
    const float  sqrtA = (float)sin(c * (double)M);   // sqrt(alpha_bar(M))
    const float  inv_c = (float)(1.0 / c);

    const int threads = 256;
    const int blocks  = (B + threads - 1) / threads;
    precond_kernel<<<blocks, threads>>>(sigma, u,
                                        ob,                 // c_skip
                                        ob + skip,          // c_out
                                        ob + skip + B,      // c_in
                                        ob + skip + 2 * B,  // c_noise
                                        B, M, skip, sqrtA, inv_c);
}